// round 16
// baseline (speedup 1.0000x reference)
#include <cuda_runtime.h>
#include <cuda_fp16.h>
#include <cstdint>

// Int8Linear: out[M,N] = f32(x[M,K] @ w[K,N]) + bias[N]
// M=16384, K=2048, N=2048. Inputs stored widened to int32 by harness
// (detected at runtime). Hybrid GEMM: legacy IMMA tensor pipe + dp4a ALU
// pipe, 64K/64K split per 128-K stage, shared int32 accumulators (exact).

#define MM 16384
#define KK 2048
#define NN 2048

#define BM 128
#define BN 128
#define BK 128
#define KTILES (KK / BK)          // 16
#define DEPTH 3
#define ROWB 144                  // padded smem row stride
#define A_SZ (BM * ROWB)
#define B_SZ (BN * ROWB)
#define STAGE (A_SZ + B_SZ)
#define DYN_SMEM (DEPTH * STAGE + 1024)

__device__ int     g_widened;
__device__ int8_t  g_x8[(size_t)MM * KK];        // 32MB packed activations
__device__ int8_t  g_wT[(size_t)NN * KK];        // 4MB transposed weight [N,K]

// ---------------------------------------------------------------- helpers
__device__ __forceinline__ uint32_t smem_u32(const void* p) {
    return (uint32_t)__cvta_generic_to_shared(p);
}
__device__ __forceinline__ void cp_async16(uint32_t dst, const void* src) {
    asm volatile("cp.async.cg.shared.global [%0], [%1], 16;" :: "r"(dst), "l"(src));
}
__device__ __forceinline__ uint32_t lds32(uint32_t a) {
    uint32_t v;
    asm volatile("ld.shared.b32 %0, [%1];" : "=r"(v) : "r"(a));
    return v;
}
__device__ __forceinline__ void lds128(uint32_t* v, uint32_t a) {
    asm volatile("ld.shared.v4.b32 {%0,%1,%2,%3}, [%4];"
                 : "=r"(v[0]), "=r"(v[1]), "=r"(v[2]), "=r"(v[3]) : "r"(a));
}
__device__ __forceinline__ void mma_s8(int* d, const uint32_t* a, const uint32_t* b) {
    asm volatile(
        "mma.sync.aligned.m16n8k32.row.col.s32.s8.s8.s32 "
        "{%0,%1,%2,%3}, {%4,%5,%6,%7}, {%8,%9}, {%0,%1,%2,%3};"
        : "+r"(d[0]), "+r"(d[1]), "+r"(d[2]), "+r"(d[3])
        : "r"(a[0]), "r"(a[1]), "r"(a[2]), "r"(a[3]), "r"(b[0]), "r"(b[1]));
}

// ---------------------------------------------------------------- detect
__global__ void detect_kernel(const int* __restrict__ w) {
    int l = threadIdx.x;
    unsigned ok = 0xFFFFFFFFu;
    #pragma unroll
    for (int j = 0; j < 2; j++) {
        int v = w[l + 32 * j];
        int hi = v >> 8;
        unsigned good = (hi == 0) || (hi == -1) ? 1u : 0u;
        ok &= __ballot_sync(0xFFFFFFFFu, good);
    }
    if (l == 0) g_widened = (ok == 0xFFFFFFFFu) ? 1 : 0;
}

// ---------------------------------------------------------------- pack x
__global__ void __launch_bounds__(256) pack_x_kernel(const void* __restrict__ xin) {
    size_t i = ((size_t)blockIdx.x * 256 + threadIdx.x) * 16;
    if (g_widened) {
        const int4* p = (const int4*)xin + (i >> 2);
        uint32_t o[4];
        #pragma unroll
        for (int j = 0; j < 4; j++) {
            int4 v = p[j];
            o[j] = (uint32_t)(v.x & 0xFF) | ((uint32_t)(v.y & 0xFF) << 8) |
                   ((uint32_t)(v.z & 0xFF) << 16) | ((uint32_t)v.w << 24);
        }
        *(uint4*)(g_x8 + i) = make_uint4(o[0], o[1], o[2], o[3]);
    } else {
        *(int4*)(g_x8 + i) = ((const int4*)xin)[i >> 4];
    }
}

// ---------------------------------------------------------------- transpose w
__global__ void __launch_bounds__(256) transpose_kernel(const void* __restrict__ win) {
    __shared__ int8_t s[32][33];
    const int n0 = blockIdx.x * 32, k0 = blockIdx.y * 32;
    const int tx = threadIdx.x;
    const int ty = threadIdx.y;
    const int wd = g_widened;
    #pragma unroll
    for (int j = 0; j < 4; j++) {
        int k = k0 + ty + 8 * j;
        int8_t v = wd ? (int8_t)(((const int*)win)[(size_t)k * NN + n0 + tx])
                      : ((const int8_t*)win)[(size_t)k * NN + n0 + tx];
        s[ty + 8 * j][tx] = v;
    }
    __syncthreads();
    #pragma unroll
    for (int j = 0; j < 4; j++) {
        int n = n0 + ty + 8 * j;
        g_wT[(size_t)n * KK + k0 + tx] = s[tx][ty + 8 * j];
    }
}

// ---------------------------------------------------------------- main GEMM
__global__ void __launch_bounds__(256) i8gemm_kernel(
    const __half* __restrict__ bias,
    float* __restrict__ out)
{
    extern __shared__ char dsm[];
    uint32_t raw = smem_u32(dsm);
    const uint32_t base = (raw + 127u) & ~127u;

    __shared__ float sbias[BN];

    const int tid = threadIdx.x;
    const int wid = tid >> 5;
    const int l   = tid & 31;
    const int g   = l >> 2;
    const int tig = l & 3;
    const int wm  = wid & 3;
    const int wn  = wid >> 2;
    const int m0  = blockIdx.y * BM;
    const int n0  = blockIdx.x * BN;

    if (tid < BN) sbias[tid] = __half2float(bias[n0 + tid]);

    const int8_t* A  = g_x8;
    const int8_t* Bt = g_wT;

    auto issue_stage = [&](int kt) {
        const int s = kt % DEPTH;
        const uint32_t sa = base + s * STAGE;
        const uint32_t sb = sa + A_SZ;
        const int8_t* ga = A  + (size_t)m0 * KK + kt * BK;
        const int8_t* gb = Bt + (size_t)n0 * KK + kt * BK;
        #pragma unroll
        for (int i = 0; i < 4; i++) {
            int c = tid + i * 256;
            int r = c >> 3, ch = c & 7;
            cp_async16(sa + (uint32_t)(r * ROWB + ch * 16), ga + (size_t)r * KK + ch * 16);
        }
        #pragma unroll
        for (int i = 0; i < 4; i++) {
            int c = tid + i * 256;
            int r = c >> 3, ch = c & 7;
            cp_async16(sb + (uint32_t)(r * ROWB + ch * 16), gb + (size_t)r * KK + ch * 16);
        }
    };

    issue_stage(0);
    asm volatile("cp.async.commit_group;" ::: "memory");
    issue_stage(1);
    asm volatile("cp.async.commit_group;" ::: "memory");

    // accumulators: acc[ma][na][c]
    //   c0: (row = wm*32 + ma*16 + g,     col = wn*64 + na*8 + tig*2)
    //   c1: col+1     c2: row+8, col      c3: row+8, col+1
    int acc[2][8][4];
    #pragma unroll
    for (int a = 0; a < 2; a++)
        #pragma unroll
        for (int b = 0; b < 8; b++)
            #pragma unroll
            for (int c = 0; c < 4; c++) acc[a][b][c] = 0;

    const uint32_t a_off = (uint32_t)((wm * 32 + g) * ROWB + tig * 4);
    const uint32_t b_off = (uint32_t)((wn * 64 + g) * ROWB + tig * 4);
    const uint32_t arow0 = (uint32_t)(wm * 32 * ROWB);
    const uint32_t brow0 = (uint32_t)(wn * 64 * ROWB);

    #pragma unroll 1
    for (int kt = 0; kt < KTILES; kt++) {
        asm volatile("cp.async.wait_group 1;" ::: "memory");
        __syncthreads();

        if (kt + DEPTH - 1 < KTILES) issue_stage(kt + DEPTH - 1);
        asm volatile("cp.async.commit_group;" ::: "memory");

        const int s = kt % DEPTH;
        const uint32_t sbase = base + s * STAGE;
        const uint32_t abuf = sbase + a_off;
        const uint32_t bbuf = sbase + A_SZ + b_off;

        // ---- IMMA half: K bytes [0, 64) of this stage (tensor pipe)
        #pragma unroll
        for (int kk = 0; kk < 2; kk++) {
            uint32_t af[2][4], bf[4][4];
            #pragma unroll
            for (int ma = 0; ma < 2; ma++) {
                uint32_t p0 = abuf + (uint32_t)(ma * 16 * ROWB + kk * 32);
                af[ma][0] = lds32(p0);
                af[ma][1] = lds32(p0 + 8 * ROWB);
                af[ma][2] = lds32(p0 + 16);
                af[ma][3] = lds32(p0 + 8 * ROWB + 16);
            }
            #pragma unroll
            for (int p = 0; p < 4; p++) {
                uint32_t p0 = bbuf + (uint32_t)(p * 16 * ROWB + kk * 32);
                bf[p][0] = lds32(p0);
                bf[p][1] = lds32(p0 + 16);
                bf[p][2] = lds32(p0 + 8 * ROWB);
                bf[p][3] = lds32(p0 + 8 * ROWB + 16);
            }
            #pragma unroll
            for (int ma = 0; ma < 2; ma++)
                #pragma unroll
                for (int p = 0; p < 4; p++) {
                    mma_s8(acc[ma][2 * p + 0], af[ma], &bf[p][0]);
                    mma_s8(acc[ma][2 * p + 1], af[ma], &bf[p][2]);
                }
        }

        // ---- dp4a half: K bytes [64, 128) of this stage (ALU pipe)
        #pragma unroll
        for (int kc = 0; kc < 4; kc++) {
            const uint32_t ko = 64 + kc * 16;
            uint32_t a4[4][4];
            #pragma unroll
            for (int r = 0; r < 4; r++)       // physical rows g, g+8, g+16, g+24
                lds128(a4[r], sbase + arow0 + (uint32_t)((g + 8 * r) * ROWB) + ko);
            #pragma unroll
            for (int h = 0; h < 2; h++) {     // 8 cols at a time (reg pressure)
                uint32_t b4[8][4];
                #pragma unroll
                for (int j = 0; j < 8; j++) { // j = (na_local<<1)|odd
                    int col = (h * 4 + (j >> 1)) * 8 + tig * 2 + (j & 1);
                    lds128(b4[j], sbase + A_SZ + brow0 + (uint32_t)(col * ROWB) + ko);
                }
                #pragma unroll
                for (int r = 0; r < 4; r++)
                    #pragma unroll
                    for (int j = 0; j < 8; j++) {
                        int* ap = &acc[r >> 1][h * 4 + (j >> 1)][(r & 1) * 2 + (j & 1)];
                        int v = *ap;
                        #pragma unroll
                        for (int q = 0; q < 4; q++)
                            v = __dp4a((int)a4[r][q], (int)b4[j][q], v);
                        *ap = v;
                    }
            }
        }
        __syncthreads();
    }

    // ---- epilogue: int32 -> f32 + bias, streaming float2 stores
    #pragma unroll
    for (int ma = 0; ma < 2; ma++) {
        #pragma unroll
        for (int na = 0; na < 8; na++) {
            int row = m0 + wm * 32 + ma * 16 + g;
            int col = n0 + wn * 64 + na * 8 + tig * 2;
            float b0 = sbias[col - n0];
            float b1 = sbias[col - n0 + 1];
            float2 v0 = make_float2((float)acc[ma][na][0] + b0,
                                    (float)acc[ma][na][1] + b1);
            float2 v1 = make_float2((float)acc[ma][na][2] + b0,
                                    (float)acc[ma][na][3] + b1);
            __stcs((float2*)&out[(size_t)row * NN + col], v0);
            __stcs((float2*)&out[(size_t)(row + 8) * NN + col], v1);
        }
    }
}

// ---------------------------------------------------------------- launch
extern "C" void kernel_launch(void* const* d_in, const int* in_sizes, int n_in,
                              void* d_out, int out_size) {
    const void*   x    = d_in[0];
    const void*   w    = d_in[1];
    const __half* bias = (const __half*)d_in[2];
    float* out = (float*)d_out;

    cudaFuncSetAttribute(i8gemm_kernel,
                         cudaFuncAttributeMaxDynamicSharedMemorySize, DYN_SMEM);

    detect_kernel<<<1, 32>>>((const int*)w);
    pack_x_kernel<<<(int)(((size_t)MM * KK) / (256 * 16)), 256>>>(x);
    transpose_kernel<<<dim3(NN / 32, KK / 32), dim3(32, 8)>>>(w);
    i8gemm_kernel<<<dim3(NN / BN, MM / BM), 256, DYN_SMEM>>>(bias, out);
}

// round 17
// speedup vs baseline: 1.2255x; 1.2255x over previous
#include <cuda_runtime.h>
#include <cuda_fp16.h>
#include <cstdint>

// Int8Linear: out[M,N] = f32(x[M,K] @ w[K,N]) + bias[N]
// M=16384, K=2048, N=2048. Inputs stored widened to int32 (runtime detect).
// Hybrid GEMM: IMMA tensor pipe (96/128 K-bytes) + dp4a fma pipe (32/128),
// register-lean + __launch_bounds__(256,2) to keep 2 CTAs/SM.

#define MM 16384
#define KK 2048
#define NN 2048

#define BM 128
#define BN 128
#define BK 128
#define KTILES (KK / BK)          // 16
#define DEPTH 3
#define ROWB 144                  // padded smem row stride
#define A_SZ (BM * ROWB)
#define B_SZ (BN * ROWB)
#define STAGE (A_SZ + B_SZ)
#define DYN_SMEM (DEPTH * STAGE + 1024)

__device__ int     g_widened;
__device__ int8_t  g_x8[(size_t)MM * KK];        // 32MB packed activations
__device__ int8_t  g_wT[(size_t)NN * KK];        // 4MB transposed weight [N,K]

// ---------------------------------------------------------------- helpers
__device__ __forceinline__ uint32_t smem_u32(const void* p) {
    return (uint32_t)__cvta_generic_to_shared(p);
}
__device__ __forceinline__ void cp_async16(uint32_t dst, const void* src) {
    asm volatile("cp.async.cg.shared.global [%0], [%1], 16;" :: "r"(dst), "l"(src));
}
__device__ __forceinline__ uint32_t lds32(uint32_t a) {
    uint32_t v;
    asm volatile("ld.shared.b32 %0, [%1];" : "=r"(v) : "r"(a));
    return v;
}
__device__ __forceinline__ void lds128(uint32_t* v, uint32_t a) {
    asm volatile("ld.shared.v4.b32 {%0,%1,%2,%3}, [%4];"
                 : "=r"(v[0]), "=r"(v[1]), "=r"(v[2]), "=r"(v[3]) : "r"(a));
}
__device__ __forceinline__ void mma_s8(int* d, const uint32_t* a, const uint32_t* b) {
    asm volatile(
        "mma.sync.aligned.m16n8k32.row.col.s32.s8.s8.s32 "
        "{%0,%1,%2,%3}, {%4,%5,%6,%7}, {%8,%9}, {%0,%1,%2,%3};"
        : "+r"(d[0]), "+r"(d[1]), "+r"(d[2]), "+r"(d[3])
        : "r"(a[0]), "r"(a[1]), "r"(a[2]), "r"(a[3]), "r"(b[0]), "r"(b[1]));
}

// ---------------------------------------------------------------- detect
__global__ void detect_kernel(const int* __restrict__ w) {
    int l = threadIdx.x;
    unsigned ok = 0xFFFFFFFFu;
    #pragma unroll
    for (int j = 0; j < 2; j++) {
        int v = w[l + 32 * j];
        int hi = v >> 8;
        unsigned good = (hi == 0) || (hi == -1) ? 1u : 0u;
        ok &= __ballot_sync(0xFFFFFFFFu, good);
    }
    if (l == 0) g_widened = (ok == 0xFFFFFFFFu) ? 1 : 0;
}

// ---------------------------------------------------------------- pack x
__global__ void __launch_bounds__(256) pack_x_kernel(const void* __restrict__ xin) {
    size_t i = ((size_t)blockIdx.x * 256 + threadIdx.x) * 16;
    if (g_widened) {
        const int4* p = (const int4*)xin + (i >> 2);
        uint32_t o[4];
        #pragma unroll
        for (int j = 0; j < 4; j++) {
            int4 v = p[j];
            o[j] = (uint32_t)(v.x & 0xFF) | ((uint32_t)(v.y & 0xFF) << 8) |
                   ((uint32_t)(v.z & 0xFF) << 16) | ((uint32_t)v.w << 24);
        }
        *(uint4*)(g_x8 + i) = make_uint4(o[0], o[1], o[2], o[3]);
    } else {
        *(int4*)(g_x8 + i) = ((const int4*)xin)[i >> 4];
    }
}

// ---------------------------------------------------------------- transpose w
__global__ void __launch_bounds__(256) transpose_kernel(const void* __restrict__ win) {
    __shared__ int8_t s[32][33];
    const int n0 = blockIdx.x * 32, k0 = blockIdx.y * 32;
    const int tx = threadIdx.x;
    const int ty = threadIdx.y;
    const int wd = g_widened;
    #pragma unroll
    for (int j = 0; j < 4; j++) {
        int k = k0 + ty + 8 * j;
        int8_t v = wd ? (int8_t)(((const int*)win)[(size_t)k * NN + n0 + tx])
                      : ((const int8_t*)win)[(size_t)k * NN + n0 + tx];
        s[ty + 8 * j][tx] = v;
    }
    __syncthreads();
    #pragma unroll
    for (int j = 0; j < 4; j++) {
        int n = n0 + ty + 8 * j;
        g_wT[(size_t)n * KK + k0 + tx] = s[tx][ty + 8 * j];
    }
}

// ---------------------------------------------------------------- main GEMM
__global__ void __launch_bounds__(256, 2) i8gemm_kernel(
    const __half* __restrict__ bias,
    float* __restrict__ out)
{
    extern __shared__ char dsm[];
    uint32_t raw = smem_u32(dsm);
    const uint32_t base = (raw + 127u) & ~127u;

    __shared__ float sbias[BN];

    const int tid = threadIdx.x;
    const int wid = tid >> 5;
    const int l   = tid & 31;
    const int g   = l >> 2;
    const int tig = l & 3;
    const int wm  = wid & 3;
    const int wn  = wid >> 2;
    const int m0  = blockIdx.y * BM;
    const int n0  = blockIdx.x * BN;

    if (tid < BN) sbias[tid] = __half2float(bias[n0 + tid]);

    const int8_t* A  = g_x8;
    const int8_t* Bt = g_wT;

    auto issue_stage = [&](int kt) {
        const int s = kt % DEPTH;
        const uint32_t sa = base + s * STAGE;
        const uint32_t sb = sa + A_SZ;
        const int8_t* ga = A  + (size_t)m0 * KK + kt * BK;
        const int8_t* gb = Bt + (size_t)n0 * KK + kt * BK;
        #pragma unroll
        for (int i = 0; i < 4; i++) {
            int c = tid + i * 256;
            int r = c >> 3, ch = c & 7;
            cp_async16(sa + (uint32_t)(r * ROWB + ch * 16), ga + (size_t)r * KK + ch * 16);
        }
        #pragma unroll
        for (int i = 0; i < 4; i++) {
            int c = tid + i * 256;
            int r = c >> 3, ch = c & 7;
            cp_async16(sb + (uint32_t)(r * ROWB + ch * 16), gb + (size_t)r * KK + ch * 16);
        }
    };

    issue_stage(0);
    asm volatile("cp.async.commit_group;" ::: "memory");
    issue_stage(1);
    asm volatile("cp.async.commit_group;" ::: "memory");

    // accumulators: acc[ma][na][c]
    //   c0: (row = wm*32 + ma*16 + g,     col = wn*64 + na*8 + tig*2)
    //   c1: col+1     c2: row+8, col      c3: row+8, col+1
    int acc[2][8][4];
    #pragma unroll
    for (int a = 0; a < 2; a++)
        #pragma unroll
        for (int b = 0; b < 8; b++)
            #pragma unroll
            for (int c = 0; c < 4; c++) acc[a][b][c] = 0;

    const uint32_t a_off = (uint32_t)((wm * 32 + g) * ROWB + tig * 4);
    const uint32_t b_off = (uint32_t)((wn * 64 + g) * ROWB + tig * 4);
    const uint32_t arow0 = (uint32_t)(wm * 32 * ROWB);
    const uint32_t brow0 = (uint32_t)(wn * 64 * ROWB);

    #pragma unroll 1
    for (int kt = 0; kt < KTILES; kt++) {
        asm volatile("cp.async.wait_group 1;" ::: "memory");
        __syncthreads();

        if (kt + DEPTH - 1 < KTILES) issue_stage(kt + DEPTH - 1);
        asm volatile("cp.async.commit_group;" ::: "memory");

        const int s = kt % DEPTH;
        const uint32_t sbase = base + s * STAGE;
        const uint32_t abuf = sbase + a_off;
        const uint32_t bbuf = sbase + A_SZ + b_off;

        // ---- IMMA part: K bytes [0, 96) of this stage (tensor pipe)
        #pragma unroll
        for (int kk = 0; kk < 3; kk++) {
            uint32_t af[2][4], bf[4][4];
            #pragma unroll
            for (int ma = 0; ma < 2; ma++) {
                uint32_t p0 = abuf + (uint32_t)(ma * 16 * ROWB + kk * 32);
                af[ma][0] = lds32(p0);
                af[ma][1] = lds32(p0 + 8 * ROWB);
                af[ma][2] = lds32(p0 + 16);
                af[ma][3] = lds32(p0 + 8 * ROWB + 16);
            }
            #pragma unroll
            for (int p = 0; p < 4; p++) {
                uint32_t p0 = bbuf + (uint32_t)(p * 16 * ROWB + kk * 32);
                bf[p][0] = lds32(p0);
                bf[p][1] = lds32(p0 + 16);
                bf[p][2] = lds32(p0 + 8 * ROWB);
                bf[p][3] = lds32(p0 + 8 * ROWB + 16);
            }
            #pragma unroll
            for (int ma = 0; ma < 2; ma++)
                #pragma unroll
                for (int p = 0; p < 4; p++) {
                    mma_s8(acc[ma][2 * p + 0], af[ma], &bf[p][0]);
                    mma_s8(acc[ma][2 * p + 1], af[ma], &bf[p][2]);
                }
        }

        // ---- dp4a part: K bytes [96, 128) of this stage (fma pipe)
        // Register-lean: a4[4][4] resident, one b4[4] at a time.
        #pragma unroll
        for (int kc = 0; kc < 2; kc++) {
            const uint32_t ko = 96 + kc * 16;
            uint32_t a4[4][4];
            #pragma unroll
            for (int r = 0; r < 4; r++)       // physical rows g, g+8, g+16, g+24
                lds128(a4[r], sbase + arow0 + (uint32_t)((g + 8 * r) * ROWB) + ko);
            #pragma unroll
            for (int j = 0; j < 16; j++) {    // j = (na<<1)|odd
                const int na  = j >> 1;
                const int odd = j & 1;
                const int col = na * 8 + tig * 2 + odd;
                uint32_t b4[4];
                lds128(b4, sbase + A_SZ + brow0 + (uint32_t)(col * ROWB) + ko);
                #pragma unroll
                for (int r = 0; r < 4; r++) {
                    int* ap = &acc[r >> 1][na][(r & 1) * 2 + odd];
                    int v = *ap;
                    #pragma unroll
                    for (int q = 0; q < 4; q++)
                        v = __dp4a((int)a4[r][q], (int)b4[q], v);
                    *ap = v;
                }
            }
        }
        __syncthreads();
    }

    // ---- epilogue: int32 -> f32 + bias, streaming float2 stores
    #pragma unroll
    for (int ma = 0; ma < 2; ma++) {
        #pragma unroll
        for (int na = 0; na < 8; na++) {
            int row = m0 + wm * 32 + ma * 16 + g;
            int col = n0 + wn * 64 + na * 8 + tig * 2;
            float b0 = sbias[col - n0];
            float b1 = sbias[col - n0 + 1];
            float2 v0 = make_float2((float)acc[ma][na][0] + b0,
                                    (float)acc[ma][na][1] + b1);
            float2 v1 = make_float2((float)acc[ma][na][2] + b0,
                                    (float)acc[ma][na][3] + b1);
            __stcs((float2*)&out[(size_t)row * NN + col], v0);
            __stcs((float2*)&out[(size_t)(row + 8) * NN + col], v1);
        }
    }
}

// ---------------------------------------------------------------- launch
extern "C" void kernel_launch(void* const* d_in, const int* in_sizes, int n_in,
                              void* d_out, int out_size) {
    const void*   x    = d_in[0];
    const void*   w    = d_in[1];
    const __half* bias = (const __half*)d_in[2];
    float* out = (float*)d_out;

    cudaFuncSetAttribute(i8gemm_kernel,
                         cudaFuncAttributeMaxDynamicSharedMemorySize, DYN_SMEM);

    detect_kernel<<<1, 32>>>((const int*)w);
    pack_x_kernel<<<(int)(((size_t)MM * KK) / (256 * 16)), 256>>>(x);
    transpose_kernel<<<dim3(NN / 32, KK / 32), dim3(32, 8)>>>(w);
    i8gemm_kernel<<<dim3(NN / BN, MM / BM), 256, DYN_SMEM>>>(bias, out);
}